// round 15
// baseline (speedup 1.0000x reference)
#include <cuda_runtime.h>

// DilateAttention: B=8, C=384 (12 heads x 32), H=W=56, kernel 3x3, dilation 2, pad 2.
// q,k,v: [B, C, H, W] f32. out: [B, H, W, C] f32.
//
// R15 = R14's exact per-thread code (1 px/thread, 32-deep guarded load batches,
// scale folded into q, direct float4 stores) with ONE change: the block->pixel
// mapping. Block = 448 threads = a full 8x56 strip of one (head, b), grid
// (7, 12, 8). All pixels that share k/v cache lines across the dilated y
// window (rows y-2/y/y+2 are reused by pixels y+-2) now run on the SAME SM,
// converting ~2/3 of neighbor loads from L2-latency (~250 cyc) misses into
// L1 hits (~39 cyc). No smem, no barriers -- scheduling only.

#define HD     32
#define HEADS  12
#define WD     56
#define HT     56
#define BD     8
#define HW     (WD * HT)
#define CTOT   (HEADS * HD)
#define NTHR   448

__global__ __launch_bounds__(NTHR, 2)
void dilate_attn_kernel(const float* __restrict__ q,
                        const float* __restrict__ k,
                        const float* __restrict__ v,
                        float* __restrict__ out)
{
    const int tid  = threadIdx.x;
    const int ly   = tid / WD;              // 0..7
    const int x    = tid - ly * WD;         // 0..55
    const int y    = blockIdx.x * 8 + ly;
    const int head = blockIdx.y;
    const int b    = blockIdx.z;

    const int base = (b * CTOT + head * HD) * HW;
    const int pix  = y * WD + x;

    const bool cL = (x >= 2);
    const bool cR = (x <= WD - 3);
    const bool yT = (y >= 2);
    const bool yB = (y <= HT - 3);

    const bool vmask[9] = {
        yT && cL, yT, yT && cR,
        cL,       true, cR,
        yB && cL, yB, yB && cR
    };
    const int voff[9] = {
        -2 * WD - 2, -2 * WD, -2 * WD + 2,
        -2,           0,       2,
         2 * WD - 2,  2 * WD,  2 * WD + 2
    };

    const float scale = 0.17677669529663687f;  // 32^-0.5

    // load q vector, scale folded in (coalesced across warp lanes)
    float qv[HD];
    {
        const float* qp = q + base + pix;
#pragma unroll
        for (int c = 0; c < HD; c++) qv[c] = qp[c * HW] * scale;
    }

    // ---- logits: per-window 32-deep independent load batches ----
    float attn[9];
    {
        const float* kc = k + base + pix;
#pragma unroll
        for (int p = 0; p < 9; p++) {
            float s = 0.0f;
            if (vmask[p]) {
                const float* kp = kc + voff[p];
#pragma unroll
                for (int c = 0; c < HD; c++) s = fmaf(qv[c], kp[c * HW], s);
            }
            attn[p] = s;   // OOB -> logit 0 (matches zero-padded unfold)
        }
    }

    // ---- softmax over 9 (normalization folded into weights) ----
    {
        float m = attn[0];
#pragma unroll
        for (int p = 1; p < 9; p++) m = fmaxf(m, attn[p]);
        float d = 0.0f;
#pragma unroll
        for (int p = 0; p < 9; p++) { attn[p] = __expf(attn[p] - m); d += attn[p]; }
        float inv = 1.0f / d;
#pragma unroll
        for (int p = 0; p < 9; p++) attn[p] *= inv;
    }

    // ---- weighted sum of v: same wide-batch structure ----
    float acc[HD];
#pragma unroll
    for (int c = 0; c < HD; c++) acc[c] = 0.0f;
    {
        const float* vc = v + base + pix;
#pragma unroll
        for (int p = 0; p < 9; p++) {
            if (vmask[p]) {
                const float w = attn[p];
                const float* vp = vc + voff[p];
#pragma unroll
                for (int c = 0; c < HD; c++) acc[c] = fmaf(w, vp[c * HW], acc[c]);
            }
        }
    }

    // ---- write out: out[b, y, x, head*32 + c] -- 128 contiguous bytes/thread ----
    float4* o = (float4*)(out + (size_t)((b * HT + y) * WD + x) * CTOT + head * HD);
#pragma unroll
    for (int c = 0; c < HD; c += 4)
        o[c / 4] = make_float4(acc[c], acc[c + 1], acc[c + 2], acc[c + 3]);
}

extern "C" void kernel_launch(void* const* d_in, const int* in_sizes, int n_in,
                              void* d_out, int out_size)
{
    const float* q = (const float*)d_in[0];
    const float* k = (const float*)d_in[1];
    const float* v = (const float*)d_in[2];
    float* out = (float*)d_out;

    dim3 grid(HT / 8, HEADS, BD);   // 7 x 12 x 8 = 672 blocks
    dilate_attn_kernel<<<grid, NTHR>>>(q, k, v, out);
}

// round 16
// speedup vs baseline: 1.1197x; 1.1197x over previous
#include <cuda_runtime.h>

// DilateAttention: B=8, C=384 (12 heads x 32), H=W=56, kernel 3x3, dilation 2, pad 2.
// q,k,v: [B, C, H, W] f32. out: [B, H, W, C] f32.
//
// R16 = R7 byte-for-byte (best measured: 2 px/thread, float2 window loads,
// per-window guards, CC=8 chunks, direct stores) with ONE change: output is
// written with __stwt streaming stores. out (38.5 MB) is write-once/never-read;
// keeping it out of L2 stops it evicting the k/v reuse window (q+k+v+out
// ~154 MB vs 126 MB L2), cutting the L2-miss latency exposure on the 9x
// k/v neighbor reuse that is the measured residual stall source.

#define HD     32
#define HEADS  12
#define WD     56
#define HT     56
#define BD     8
#define HW     (WD * HT)
#define CTOT   384
#define XG     28          // x-pairs per row
#define NTHR   256
#define CC     8
#define NCH    (HD / CC)   // 4

__global__ __launch_bounds__(NTHR, 4)
void dilate_attn_kernel(const float* __restrict__ q,
                        const float* __restrict__ k,
                        const float* __restrict__ v,
                        float* __restrict__ out)
{
    const int gid  = blockIdx.x * NTHR + threadIdx.x;
    const int xg   = gid % XG;
    int r1         = gid / XG;
    const int y    = r1 % HT;
    int r2         = r1 / HT;
    const int head = r2 % HEADS;
    const int b    = r2 / HEADS;
    const int x0   = xg * 2;

    const int base = (b * CTOT + head * HD) * HW;
    const int pix  = y * WD + x0;

    const bool cL = (x0 >= 2);
    const bool cR = (x0 <= WD - 4);
    const bool yT = (y >= 2);
    const bool yB = (y <= HT - 3);

    const bool vmask[9] = {
        yT && cL, yT, yT && cR,
        cL,       true, cR,
        yB && cL, yB, yB && cR
    };
    const int voff[9] = {
        -2 * WD - 2, -2 * WD, -2 * WD + 2,
        -2,           0,       2,
         2 * WD - 2,  2 * WD,  2 * WD + 2
    };

    const float* qc = q + base + pix;
    const float* kc = k + base + pix;
    const float* vc = v + base + pix;

    const float scale = 0.17677669529663687f;  // 32^-0.5

    float a0[9], a1[9];
#pragma unroll
    for (int p = 0; p < 9; p++) { a0[p] = 0.0f; a1[p] = 0.0f; }

    // ================= K phase: logits, channel chunks of 8 =================
#pragma unroll
    for (int ch = 0; ch < NCH; ch++) {
        float2 qv[CC];
#pragma unroll
        for (int c = 0; c < CC; c++) {
            qv[c] = *(const float2*)(qc + (ch * CC + c) * HW);
            qv[c].x *= scale; qv[c].y *= scale;
        }

#pragma unroll
        for (int p = 0; p < 9; p++) {
            if (vmask[p]) {
                const float* kp = kc + ch * CC * HW + voff[p];
                float s0 = a0[p], s1 = a1[p];
#pragma unroll
                for (int c = 0; c < CC; c++) {
                    float2 kv = *(const float2*)(kp + c * HW);
                    s0 = fmaf(qv[c].x, kv.x, s0);
                    s1 = fmaf(qv[c].y, kv.y, s1);
                }
                a0[p] = s0; a1[p] = s1;
            }
        }
    }

    // ================= softmax (normalization folded into weights) =================
    {
        float m0 = -1e30f, m1 = -1e30f;
#pragma unroll
        for (int p = 0; p < 9; p++) { m0 = fmaxf(m0, a0[p]); m1 = fmaxf(m1, a1[p]); }
        float d0 = 0.0f, d1 = 0.0f;
#pragma unroll
        for (int p = 0; p < 9; p++) {
            a0[p] = __expf(a0[p] - m0); d0 += a0[p];
            a1[p] = __expf(a1[p] - m1); d1 += a1[p];
        }
        float i0 = 1.0f / d0, i1 = 1.0f / d1;
#pragma unroll
        for (int p = 0; p < 9; p++) { a0[p] *= i0; a1[p] *= i1; }
    }

    // ================= V phase: weighted sum + streaming stores =================
    const int ob = ((b * HT + y) * WD + x0) * CTOT + head * HD;

#pragma unroll
    for (int ch = 0; ch < NCH; ch++) {
        float acc0[CC], acc1[CC];
#pragma unroll
        for (int c = 0; c < CC; c++) { acc0[c] = 0.0f; acc1[c] = 0.0f; }

#pragma unroll
        for (int p = 0; p < 9; p++) {
            if (vmask[p]) {
                const float w0 = a0[p], w1 = a1[p];
                const float* vp = vc + ch * CC * HW + voff[p];
#pragma unroll
                for (int c = 0; c < CC; c++) {
                    float2 vv = *(const float2*)(vp + c * HW);
                    acc0[c] = fmaf(w0, vv.x, acc0[c]);
                    acc1[c] = fmaf(w1, vv.y, acc1[c]);
                }
            }
        }

        float* o0 = out + ob + ch * CC;
        __stwt((float4*)(o0),            make_float4(acc0[0], acc0[1], acc0[2], acc0[3]));
        __stwt((float4*)(o0 + 4),        make_float4(acc0[4], acc0[5], acc0[6], acc0[7]));
        __stwt((float4*)(o0 + CTOT),     make_float4(acc1[0], acc1[1], acc1[2], acc1[3]));
        __stwt((float4*)(o0 + CTOT + 4), make_float4(acc1[4], acc1[5], acc1[6], acc1[7]));
    }
}

extern "C" void kernel_launch(void* const* d_in, const int* in_sizes, int n_in,
                              void* d_out, int out_size)
{
    const float* q = (const float*)d_in[0];
    const float* k = (const float*)d_in[1];
    const float* v = (const float*)d_in[2];
    float* out = (float*)d_out;

    int total  = BD * HEADS * HT * XG;   // 150528 threads (2 px each)
    int blocks = total / NTHR;           // 588
    dilate_attn_kernel<<<blocks, NTHR>>>(q, k, v, out);
}